// round 12
// baseline (speedup 1.0000x reference)
#include <cuda_runtime.h>

// VanillaRNN persistent kernel for GB300 (sm_103a) — round 12.
// h_{t+1} = tanh(W_hx * x_t + W_hh @ h_t + b_h), 1024 steps; p = W_ph @ h + b_p.
//
// 128 persistent CTAs = 16 row-groups x 8 batch-groups, 32x32 tile each.
// R11 core (W in registers, broadcast h LDS) + exchange de-serialization:
//  - PER-WARP-PRIVATE refresh: warp w loads exactly its own k-slice chunk
//    (j0 == wid). No block sync between refresh and compute; flag-wait and
//    LDG latency overlap with other warps' compute.
//  - 2 syncthreads per step (was 3).
//  - reduction scratch stride 33 (odd): conflict-free scalar STS/LDS.

#define HH    512
#define BB    256
#define TT    1024
#define NCLS  10

#define RGN   16
#define BGN   8
#define HR    32
#define BT    32
#define NCTA  (RGN * BGN)
#define NTHR  512

#define H_PAD 36
#define CSTR  33                          // reduction scratch stride (odd!)

#define SMEM_FLOATS (HH * H_PAD + 16 * 32 * CSTR + BT)
#define SMEM_BYTES  (SMEM_FLOATS * 4)     // ~138 KB

__device__ float    g_h[3][HH][BB];        // triple-buffered hidden state
__device__ unsigned g_flag[BGN][RGN][32];  // per-tile publish counters, 128B apart

__device__ __forceinline__ void wait_flag(const unsigned* p, unsigned target) {
    unsigned v;
    do {
        asm volatile("ld.acquire.gpu.u32 %0, [%1];" : "=r"(v) : "l"(p) : "memory");
    } while (v < target);
}

__global__ void __launch_bounds__(NTHR, 1) rnn_persistent(
    const float* __restrict__ x,       // [BB][TT]
    const float* __restrict__ h_init,  // [HH]
    const float* __restrict__ W_hx,    // [HH]
    const float* __restrict__ W_hh,    // [HH][HH]
    const float* __restrict__ b_h,     // [HH]
    const float* __restrict__ W_ph,    // [NCLS][HH]
    const float* __restrict__ b_p,     // [NCLS]
    float* __restrict__ out)           // [BB][NCLS]
{
    extern __shared__ float smem[];
    float* hs  = smem;                        // [HH][H_PAD]
    float* red = smem + HH * H_PAD;           // [16][32][CSTR]
    float* xs  = red + 16 * 32 * CSTR;        // [BT]

    const int tid   = threadIdx.x;
    const int lane  = tid & 31;
    const int wid   = tid >> 5;        // 0..15 : k-slice AND refresh chunk
    const int cta   = blockIdx.x;
    const int rg    = cta >> 3;
    const int bg    = cta & 7;
    const int rbase = rg * HR;
    const int cbase = bg * BT;
    const int k0    = wid << 5;

    // ---- W_hh slice for this thread: row=lane, k in [k0,k0+32) -> registers ----
    float4 W4[8];
    {
        const float* wsrc = W_hh + (rbase + lane) * HH + k0;
        #pragma unroll
        for (int j = 0; j < 8; ++j)
            W4[j] = *reinterpret_cast<const float4*>(wsrc + (j << 2));
    }

    // ---- init hs with h_init broadcast (step 0 reads this) ----
    for (int k = tid; k < HH; k += NTHR) {
        float v = h_init[k];
        float* row = hs + k * H_PAD;
        #pragma unroll
        for (int c = 0; c < BT; ++c) row[c] = v;
    }

    // ---- reduce/publish mapping: thread -> (row ro, col pair cp) ----
    const int ro = tid >> 4;            // 0..31
    const int cp = (tid & 15) << 1;     // 0,2,...,30
    const float bh = b_h[rbase + ro];
    const float wx = W_hx[rbase + ro];

    // ---- refresh lane mapping (within own chunk wid) ----
    const int lk  = lane >> 3;          // 0..3
    const int lc4 = (lane & 7) << 2;    // 0,4,...,28

    const unsigned* myflag = &g_flag[bg][wid][0];
    float* hslice = hs + k0 * H_PAD;

    __syncthreads();

    for (int s = 0; s < TT; ++s) {
        // ---- per-warp-private refresh of OWN k-slice (skip step 0) ----
        if (s > 0) {
            const int rbuf = s % 3;
            if (lane == 0) wait_flag(myflag, (unsigned)s);
            __syncwarp();
            const float* src = &g_h[rbuf][k0][cbase];
            #pragma unroll
            for (int p = 0; p < 8; ++p) {
                int k = (p << 2) + lk;
                float4 v = __ldcg(reinterpret_cast<const float4*>(src + k * BB + lc4));
                *reinterpret_cast<float4*>(hslice + k * H_PAD + lc4) = v;
            }
            __syncwarp();
        }
        if (tid < BT) xs[tid] = x[(cbase + tid) * TT + s];

        // ---- partial GEMV: row=lane, own 32 k's, all 32 cols (broadcast LDS) ----
        float4 A[8];
        #pragma unroll
        for (int q = 0; q < 8; ++q) A[q] = make_float4(0.f, 0.f, 0.f, 0.f);

        #pragma unroll
        for (int kc = 0; kc < 8; ++kc) {
            const float4 w  = W4[kc];
            const float* hr = hslice + (kc << 2) * H_PAD;
            #pragma unroll
            for (int q = 0; q < 8; ++q) {
                const float4 ha = *reinterpret_cast<const float4*>(hr + (q << 2));
                A[q].x = fmaf(w.x, ha.x, A[q].x); A[q].y = fmaf(w.x, ha.y, A[q].y);
                A[q].z = fmaf(w.x, ha.z, A[q].z); A[q].w = fmaf(w.x, ha.w, A[q].w);
            }
            #pragma unroll
            for (int q = 0; q < 8; ++q) {
                const float4 ha = *reinterpret_cast<const float4*>(hr + H_PAD + (q << 2));
                A[q].x = fmaf(w.y, ha.x, A[q].x); A[q].y = fmaf(w.y, ha.y, A[q].y);
                A[q].z = fmaf(w.y, ha.z, A[q].z); A[q].w = fmaf(w.y, ha.w, A[q].w);
            }
            #pragma unroll
            for (int q = 0; q < 8; ++q) {
                const float4 ha = *reinterpret_cast<const float4*>(hr + 2 * H_PAD + (q << 2));
                A[q].x = fmaf(w.z, ha.x, A[q].x); A[q].y = fmaf(w.z, ha.y, A[q].y);
                A[q].z = fmaf(w.z, ha.z, A[q].z); A[q].w = fmaf(w.z, ha.w, A[q].w);
            }
            #pragma unroll
            for (int q = 0; q < 8; ++q) {
                const float4 ha = *reinterpret_cast<const float4*>(hr + 3 * H_PAD + (q << 2));
                A[q].x = fmaf(w.w, ha.x, A[q].x); A[q].y = fmaf(w.w, ha.y, A[q].y);
                A[q].z = fmaf(w.w, ha.z, A[q].z); A[q].w = fmaf(w.w, ha.w, A[q].w);
            }
        }

        // ---- write partials (conflict-free: stride 33, lanes hit 32 banks) ----
        float* myred = red + ((wid << 5) + lane) * CSTR;
        #pragma unroll
        for (int q = 0; q < 8; ++q) {
            myred[(q << 2) + 0] = A[q].x;
            myred[(q << 2) + 1] = A[q].y;
            myred[(q << 2) + 2] = A[q].z;
            myred[(q << 2) + 3] = A[q].w;
        }
        __syncthreads();

        // ---- reduce 16 k-slice partials, finish, publish ----
        {
            const float* rr = red + ro * CSTR + cp;
            float s0 = 0.f, s1 = 0.f;
            #pragma unroll
            for (int w = 0; w < 16; ++w) {
                s0 += rr[(w << 5) * CSTR];
                s1 += rr[(w << 5) * CSTR + 1];
            }
            float v0 = tanhf(s0 + fmaf(wx, xs[cp],     bh));
            float v1 = tanhf(s1 + fmaf(wx, xs[cp + 1], bh));
            const int wbuf = (s + 1) % 3;
            *reinterpret_cast<float2*>(&g_h[wbuf][rbase + ro][cbase + cp]) =
                make_float2(v0, v1);
        }

        __syncthreads();
        if (tid == 0)
            asm volatile("st.release.gpu.u32 [%0], %1;"
                         :: "l"(&g_flag[bg][rg][0]), "r"((unsigned)(s + 1)) : "memory");
    }

    // ---- final projection (row-group 0 CTAs); h_1024 in buf 1024%3 == 1 ----
    if (rg == 0) {
        {
            if (lane == 0) wait_flag(myflag, (unsigned)TT);
            __syncwarp();
            const int rbuf = TT % 3;
            const float* src = &g_h[rbuf][k0][cbase];
            #pragma unroll
            for (int p = 0; p < 8; ++p) {
                int k = (p << 2) + lk;
                float4 v = __ldcg(reinterpret_cast<const float4*>(src + k * BB + lc4));
                *reinterpret_cast<float4*>(hslice + k * H_PAD + lc4) = v;
            }
        }
        __syncthreads();

        // reuse reduction buffer for W_ph (10*512 floats)
        float* Wp = red;
        for (int i = tid; i < (NCLS * HH) / 4; i += NTHR) {
            float4 v = *reinterpret_cast<const float4*>(W_ph + (i << 2));
            *reinterpret_cast<float4*>(Wp + (i << 2)) = v;
        }
        __syncthreads();

        for (int idx = tid; idx < BT * NCLS; idx += NTHR) {
            int cl = idx / NCLS;
            int n  = idx - cl * NCLS;
            float acc = b_p[n];
            const float* wrow = Wp + n * HH;
            const float* hcol = hs + cl;
            #pragma unroll 8
            for (int k = 0; k < HH; ++k)
                acc = fmaf(wrow[k], hcol[k * H_PAD], acc);
            out[(cbase + cl) * NCLS + n] = acc;
        }
    }
}

extern "C" void kernel_launch(void* const* d_in, const int* in_sizes, int n_in,
                              void* d_out, int out_size) {
    const float* x      = (const float*)d_in[0];
    const float* h_init = (const float*)d_in[1];
    const float* W_hx   = (const float*)d_in[2];
    const float* W_hh   = (const float*)d_in[3];
    const float* b_h    = (const float*)d_in[4];
    const float* W_ph   = (const float*)d_in[5];
    const float* b_p    = (const float*)d_in[6];
    float* out = (float*)d_out;

    void* flagp = nullptr;
    cudaGetSymbolAddress(&flagp, g_flag);
    cudaMemsetAsync(flagp, 0, BGN * RGN * 32 * sizeof(unsigned), 0);

    cudaFuncSetAttribute(rnn_persistent,
                         cudaFuncAttributeMaxDynamicSharedMemorySize, SMEM_BYTES);

    rnn_persistent<<<NCTA, NTHR, SMEM_BYTES, 0>>>(x, h_init, W_hx, W_hh, b_h,
                                                  W_ph, b_p, out);
}

// round 13
// speedup vs baseline: 1.1689x; 1.1689x over previous
#include <cuda_runtime.h>

// VanillaRNN persistent kernel for GB300 (sm_103a) — round 13.
// h_{t+1} = tanh(W_hx * x_t + W_hh @ h_t + b_h), 1024 steps; p = W_ph @ h + b_p.
//
// R11 skeleton (best: W-in-regs, broadcast h, distributed refresh, per-tile
// flags, triple buffer) with crossbar relief in the compute mapping:
//  - lane = (kh = lane>>4, rp = lane&15): rows {2rp, 2rp+1}, k = k0 + 2i + kh.
//    Each h LDS.128 now carries TWO distinct 16B chunks (kh-pair, 36-float
//    apart -> disjoint bank quads) -> h wavefronts halve: 4096 -> 2048 /SM/step.
//  - kh-halves combined with 32 shfl_xor(16) (each lane sends the row its
//    partner keeps), then the SAME red[16][32][36] STS / reduce / publish as R11.

#define HH    512
#define BB    256
#define TT    1024
#define NCLS  10

#define RGN   16
#define BGN   8
#define HR    32
#define BT    32
#define NCTA  (RGN * BGN)
#define NTHR  512

#define H_PAD 36
#define CSTR  36

#define SMEM_FLOATS (HH * H_PAD + 16 * 32 * CSTR + BT)
#define SMEM_BYTES  (SMEM_FLOATS * 4)     // ~143 KB

__device__ float    g_h[3][HH][BB];        // triple-buffered hidden state
__device__ unsigned g_flag[BGN][RGN][32];  // per-tile publish counters, 128B apart

__device__ __forceinline__ void wait_flag(const unsigned* p, unsigned target) {
    unsigned v;
    do {
        asm volatile("ld.acquire.gpu.u32 %0, [%1];" : "=r"(v) : "l"(p) : "memory");
    } while (v < target);
}

__global__ void __launch_bounds__(NTHR, 1) rnn_persistent(
    const float* __restrict__ x,       // [BB][TT]
    const float* __restrict__ h_init,  // [HH]
    const float* __restrict__ W_hx,    // [HH]
    const float* __restrict__ W_hh,    // [HH][HH]
    const float* __restrict__ b_h,     // [HH]
    const float* __restrict__ W_ph,    // [NCLS][HH]
    const float* __restrict__ b_p,     // [NCLS]
    float* __restrict__ out)           // [BB][NCLS]
{
    extern __shared__ float smem[];
    float* hs  = smem;                        // [HH][H_PAD]
    float* red = smem + HH * H_PAD;           // [16][32][CSTR]
    float* xs  = red + 16 * 32 * CSTR;        // [BT]

    const int tid   = threadIdx.x;
    const int lane  = tid & 31;
    const int wid   = tid >> 5;        // 0..15 : k-slice
    const int cta   = blockIdx.x;
    const int rg    = cta >> 3;
    const int bg    = cta & 7;
    const int rbase = rg * HR;
    const int cbase = bg * BT;
    const int k0    = wid << 5;

    // ---- compute-lane mapping: 2 rows, 16 interleaved k per lane ----
    const int kh = lane >> 4;          // k parity
    const int rp = lane & 15;          // row pair index
    const int r0 = rp << 1;            // rows r0, r0+1

    // ---- W_hh values for this thread -> 32 registers (one-time gather) ----
    float w0[16], w1[16];
    {
        const float* wr0 = W_hh + (rbase + r0)     * HH + k0 + kh;
        const float* wr1 = W_hh + (rbase + r0 + 1) * HH + k0 + kh;
        #pragma unroll
        for (int i = 0; i < 16; ++i) {
            w0[i] = wr0[i << 1];
            w1[i] = wr1[i << 1];
        }
    }

    // ---- init hs with h_init broadcast (step 0 reads this) ----
    for (int k = tid; k < HH; k += NTHR) {
        float v = h_init[k];
        float* row = hs + k * H_PAD;
        #pragma unroll
        for (int c = 0; c < BT; ++c) row[c] = v;
    }

    // ---- reduce/publish mapping: thread -> (row ro, col pair cp) ----
    const int ro = tid >> 4;            // 0..31
    const int cp = (tid & 15) << 1;     // 0,2,...,30
    const float bh = b_h[rbase + ro];
    const float wx = W_hx[rbase + ro];

    // ---- refresh mapping: warp wid handles chunk (rg+wid)&15 (R11-proven) ----
    const int j0  = (rg + wid) & 15;
    const int lk  = lane >> 3;
    const int lc4 = (lane & 7) << 2;

    __syncthreads();

    for (int s = 0; s < TT; ++s) {
        // ---- distributed refresh, all warps in parallel (skip step 0) ----
        if (s > 0) {
            const int rbuf = s % 3;
            if (lane == 0) wait_flag(&g_flag[bg][j0][0], (unsigned)s);
            __syncwarp();
            const float* src = &g_h[rbuf][j0 << 5][cbase];
            float*       dst = hs + (j0 << 5) * H_PAD;
            #pragma unroll
            for (int p = 0; p < 8; ++p) {
                int k = (p << 2) + lk;
                float4 v = __ldcg(reinterpret_cast<const float4*>(src + k * BB + lc4));
                *reinterpret_cast<float4*>(dst + k * H_PAD + lc4) = v;
            }
        }
        if (tid < BT) xs[tid] = x[(cbase + tid) * TT + s];
        __syncthreads();

        // ---- partial GEMV: 2 rows x 16 k x 32 cols; kh-paired broadcast LDS ----
        float4 A0[8], A1[8];
        #pragma unroll
        for (int q = 0; q < 8; ++q) {
            A0[q] = make_float4(0.f, 0.f, 0.f, 0.f);
            A1[q] = make_float4(0.f, 0.f, 0.f, 0.f);
        }

        const float* hbase = hs + (k0 + kh) * H_PAD;
        #pragma unroll
        for (int i = 0; i < 16; ++i) {
            const float  wa = w0[i];
            const float  wb = w1[i];
            const float* hr = hbase + (i << 1) * H_PAD;
            #pragma unroll
            for (int q = 0; q < 8; ++q) {
                const float4 ha = *reinterpret_cast<const float4*>(hr + (q << 2));
                A0[q].x = fmaf(wa, ha.x, A0[q].x); A0[q].y = fmaf(wa, ha.y, A0[q].y);
                A0[q].z = fmaf(wa, ha.z, A0[q].z); A0[q].w = fmaf(wa, ha.w, A0[q].w);
                A1[q].x = fmaf(wb, ha.x, A1[q].x); A1[q].y = fmaf(wb, ha.y, A1[q].y);
                A1[q].z = fmaf(wb, ha.z, A1[q].z); A1[q].w = fmaf(wb, ha.w, A1[q].w);
            }
        }

        // ---- combine kh-halves: send the row the partner keeps ----
        // lane kh=0 keeps row r0 (A0), receives partner's A0; kh=1 keeps r0+1.
        const int myrow = r0 + kh;
        float* myred = red + ((wid << 5) + myrow) * CSTR;
        #pragma unroll
        for (int q = 0; q < 8; ++q) {
            float4 send = kh ? A0[q] : A1[q];
            float4 keep = kh ? A1[q] : A0[q];
            float4 rec;
            rec.x = __shfl_xor_sync(0xffffffffu, send.x, 16);
            rec.y = __shfl_xor_sync(0xffffffffu, send.y, 16);
            rec.z = __shfl_xor_sync(0xffffffffu, send.z, 16);
            rec.w = __shfl_xor_sync(0xffffffffu, send.w, 16);
            keep.x += rec.x; keep.y += rec.y; keep.z += rec.z; keep.w += rec.w;
            *reinterpret_cast<float4*>(myred + (q << 2)) = keep;
        }
        __syncthreads();

        // ---- reduce 16 k-slice partials, finish, publish (R11-identical) ----
        {
            const float* rr = red + ro * CSTR + cp;
            float s0 = 0.f, s1 = 0.f;
            #pragma unroll
            for (int w = 0; w < 16; ++w) {
                s0 += rr[(w << 5) * CSTR];
                s1 += rr[(w << 5) * CSTR + 1];
            }
            float v0 = tanhf(s0 + fmaf(wx, xs[cp],     bh));
            float v1 = tanhf(s1 + fmaf(wx, xs[cp + 1], bh));
            const int wbuf = (s + 1) % 3;
            *reinterpret_cast<float2*>(&g_h[wbuf][rbase + ro][cbase + cp]) =
                make_float2(v0, v1);
        }

        __syncthreads();
        if (tid == 0)
            asm volatile("st.release.gpu.u32 [%0], %1;"
                         :: "l"(&g_flag[bg][rg][0]), "r"((unsigned)(s + 1)) : "memory");
    }

    // ---- final projection (row-group 0 CTAs); h_1024 in buf 1024%3 == 1 ----
    if (rg == 0) {
        {
            if (lane == 0) wait_flag(&g_flag[bg][j0][0], (unsigned)TT);
            __syncwarp();
            const int rbuf = TT % 3;
            const float* src = &g_h[rbuf][j0 << 5][cbase];
            float*       dst = hs + (j0 << 5) * H_PAD;
            #pragma unroll
            for (int p = 0; p < 8; ++p) {
                int k = (p << 2) + lk;
                float4 v = __ldcg(reinterpret_cast<const float4*>(src + k * BB + lc4));
                *reinterpret_cast<float4*>(dst + k * H_PAD + lc4) = v;
            }
        }
        __syncthreads();

        // reuse reduction buffer for W_ph (10*512 floats)
        float* Wp = red;
        for (int i = tid; i < (NCLS * HH) / 4; i += NTHR) {
            float4 v = *reinterpret_cast<const float4*>(W_ph + (i << 2));
            *reinterpret_cast<float4*>(Wp + (i << 2)) = v;
        }
        __syncthreads();

        for (int idx = tid; idx < BT * NCLS; idx += NTHR) {
            int cl = idx / NCLS;
            int n  = idx - cl * NCLS;
            float acc = b_p[n];
            const float* wrow = Wp + n * HH;
            const float* hcol = hs + cl;
            #pragma unroll 8
            for (int k = 0; k < HH; ++k)
                acc = fmaf(wrow[k], hcol[k * H_PAD], acc);
            out[(cbase + cl) * NCLS + n] = acc;
        }
    }
}

extern "C" void kernel_launch(void* const* d_in, const int* in_sizes, int n_in,
                              void* d_out, int out_size) {
    const float* x      = (const float*)d_in[0];
    const float* h_init = (const float*)d_in[1];
    const float* W_hx   = (const float*)d_in[2];
    const float* W_hh   = (const float*)d_in[3];
    const float* b_h    = (const float*)d_in[4];
    const float* W_ph   = (const float*)d_in[5];
    const float* b_p    = (const float*)d_in[6];
    float* out = (float*)d_out;

    void* flagp = nullptr;
    cudaGetSymbolAddress(&flagp, g_flag);
    cudaMemsetAsync(flagp, 0, BGN * RGN * 32 * sizeof(unsigned), 0);

    cudaFuncSetAttribute(rnn_persistent,
                         cudaFuncAttributeMaxDynamicSharedMemorySize, SMEM_BYTES);

    rnn_persistent<<<NCTA, NTHR, SMEM_BYTES, 0>>>(x, h_init, W_hx, W_hh, b_h,
                                                  W_ph, b_p, out);
}

// round 15
// speedup vs baseline: 1.1741x; 1.0044x over previous
#include <cuda_runtime.h>

// VanillaRNN persistent kernel for GB300 (sm_103a) — round 14: FFMA2 on R13.
// h_{t+1} = tanh(W_hx * x_t + W_hh @ h_t + b_h), 1024 steps; p = W_ph @ h + b_p.
//
// R13 skeleton (best, 6053us) with the inner GEMV converted to packed f32x2:
//  - acc = u64 col-pairs P0/P1[16] (same reg footprint as float4 A0/A1[8]).
//  - h pairs via ld.shared.v2.u64 (bit-identical addresses to R13's LDS.128,
//    same 2048 wavefronts/SM/step).
//  - W stays in 32 scalar regs; 2 mov.b64 dup-packs per i amortize over 32
//    FFMA2 -> per-thread inner issue 1152 -> ~672; issue/SMSP ~5.3K -> ~3.6K.
//  - combine/reduce/publish/refresh/flags identical to R13.

#define HH    512
#define BB    256
#define TT    1024
#define NCLS  10

#define RGN   16
#define BGN   8
#define HR    32
#define BT    32
#define NCTA  (RGN * BGN)
#define NTHR  512

#define H_PAD 36
#define CSTR  36

#define SMEM_FLOATS (HH * H_PAD + 16 * 32 * CSTR + BT)
#define SMEM_BYTES  (SMEM_FLOATS * 4)     // ~143 KB

typedef unsigned long long u64;

__device__ float    g_h[3][HH][BB];        // triple-buffered hidden state
__device__ unsigned g_flag[BGN][RGN][32];  // per-tile publish counters, 128B apart

__device__ __forceinline__ void wait_flag(const unsigned* p, unsigned target) {
    unsigned v;
    do {
        asm volatile("ld.acquire.gpu.u32 %0, [%1];" : "=r"(v) : "l"(p) : "memory");
    } while (v < target);
}

__device__ __forceinline__ u64 ffma2(u64 a, u64 b, u64 c) {
    u64 d;
    asm("fma.rn.f32x2 %0, %1, %2, %3;" : "=l"(d) : "l"(a), "l"(b), "l"(c));
    return d;
}

__global__ void __launch_bounds__(NTHR, 1) rnn_persistent(
    const float* __restrict__ x,       // [BB][TT]
    const float* __restrict__ h_init,  // [HH]
    const float* __restrict__ W_hx,    // [HH]
    const float* __restrict__ W_hh,    // [HH][HH]
    const float* __restrict__ b_h,     // [HH]
    const float* __restrict__ W_ph,    // [NCLS][HH]
    const float* __restrict__ b_p,     // [NCLS]
    float* __restrict__ out)           // [BB][NCLS]
{
    extern __shared__ float smem[];
    float* hs  = smem;                        // [HH][H_PAD]
    float* red = smem + HH * H_PAD;           // [16][32][CSTR]
    float* xs  = red + 16 * 32 * CSTR;        // [BT]

    const int tid   = threadIdx.x;
    const int lane  = tid & 31;
    const int wid   = tid >> 5;        // 0..15 : k-slice
    const int cta   = blockIdx.x;
    const int rg    = cta >> 3;
    const int bg    = cta & 7;
    const int rbase = rg * HR;
    const int cbase = bg * BT;
    const int k0    = wid << 5;

    // ---- compute-lane mapping: 2 rows, 16 interleaved k per lane ----
    const int kh = lane >> 4;          // k parity
    const int rp = lane & 15;          // row pair index
    const int r0 = rp << 1;            // rows r0, r0+1

    // ---- W_hh values for this thread -> 32 scalar registers ----
    float w0[16], w1[16];
    {
        const float* wr0 = W_hh + (rbase + r0)     * HH + k0 + kh;
        const float* wr1 = W_hh + (rbase + r0 + 1) * HH + k0 + kh;
        #pragma unroll
        for (int i = 0; i < 16; ++i) {
            w0[i] = wr0[i << 1];
            w1[i] = wr1[i << 1];
        }
    }

    // ---- init hs with h_init broadcast (step 0 reads this) ----
    for (int k = tid; k < HH; k += NTHR) {
        float v = h_init[k];
        float* row = hs + k * H_PAD;
        #pragma unroll
        for (int c = 0; c < BT; ++c) row[c] = v;
    }

    // ---- reduce/publish mapping: thread -> (row ro, col pair cp) ----
    const int ro = tid >> 4;            // 0..31
    const int cp = (tid & 15) << 1;     // 0,2,...,30
    const float bh = b_h[rbase + ro];
    const float wx = W_hx[rbase + ro];

    // ---- refresh mapping: warp wid handles chunk (rg+wid)&15 ----
    const int j0  = (rg + wid) & 15;
    const int lk  = lane >> 3;
    const int lc4 = (lane & 7) << 2;

    // shared address of this lane's h base (k = k0 + kh)
    const unsigned hb_s =
        (unsigned)__cvta_generic_to_shared(hs + (k0 + kh) * H_PAD);

    __syncthreads();

    for (int s = 0; s < TT; ++s) {
        // ---- distributed refresh, all warps in parallel (skip step 0) ----
        if (s > 0) {
            const int rbuf = s % 3;
            if (lane == 0) wait_flag(&g_flag[bg][j0][0], (unsigned)s);
            __syncwarp();
            const float* src = &g_h[rbuf][j0 << 5][cbase];
            float*       dst = hs + (j0 << 5) * H_PAD;
            #pragma unroll
            for (int p = 0; p < 8; ++p) {
                int k = (p << 2) + lk;
                float4 v = __ldcg(reinterpret_cast<const float4*>(src + k * BB + lc4));
                *reinterpret_cast<float4*>(dst + k * H_PAD + lc4) = v;
            }
        }
        if (tid < BT) xs[tid] = x[(cbase + tid) * TT + s];
        __syncthreads();

        // ---- packed partial GEMV: 2 rows x 16 k x 32 cols via FFMA2 ----
        u64 P0[16], P1[16];
        #pragma unroll
        for (int q = 0; q < 16; ++q) { P0[q] = 0ull; P1[q] = 0ull; }

        #pragma unroll
        for (int i = 0; i < 16; ++i) {
            u64 dw0, dw1;
            asm("mov.b64 %0, {%1, %1};" : "=l"(dw0) : "f"(w0[i]));
            asm("mov.b64 %0, {%1, %1};" : "=l"(dw1) : "f"(w1[i]));
            const unsigned hr = hb_s + (unsigned)((i << 1) * (H_PAD * 4));
            #pragma unroll
            for (int q = 0; q < 8; ++q) {
                u64 hA, hB;
                asm("ld.shared.v2.u64 {%0, %1}, [%2];"
                    : "=l"(hA), "=l"(hB) : "r"(hr + (q << 4)));
                P0[2*q]     = ffma2(dw0, hA, P0[2*q]);
                P0[2*q + 1] = ffma2(dw0, hB, P0[2*q + 1]);
                P1[2*q]     = ffma2(dw1, hA, P1[2*q]);
                P1[2*q + 1] = ffma2(dw1, hB, P1[2*q + 1]);
            }
        }

        // ---- unpack to float4s for the (unchanged) combine path ----
        float4 A0[8], A1[8];
        #pragma unroll
        for (int q = 0; q < 8; ++q) {
            asm("mov.b64 {%0, %1}, %2;" : "=f"(A0[q].x), "=f"(A0[q].y) : "l"(P0[2*q]));
            asm("mov.b64 {%0, %1}, %2;" : "=f"(A0[q].z), "=f"(A0[q].w) : "l"(P0[2*q+1]));
            asm("mov.b64 {%0, %1}, %2;" : "=f"(A1[q].x), "=f"(A1[q].y) : "l"(P1[2*q]));
            asm("mov.b64 {%0, %1}, %2;" : "=f"(A1[q].z), "=f"(A1[q].w) : "l"(P1[2*q+1]));
        }

        // ---- combine kh-halves: send the row the partner keeps ----
        const int myrow = r0 + kh;
        float* myred = red + ((wid << 5) + myrow) * CSTR;
        #pragma unroll
        for (int q = 0; q < 8; ++q) {
            float4 send = kh ? A0[q] : A1[q];
            float4 keep = kh ? A1[q] : A0[q];
            float4 rec;
            rec.x = __shfl_xor_sync(0xffffffffu, send.x, 16);
            rec.y = __shfl_xor_sync(0xffffffffu, send.y, 16);
            rec.z = __shfl_xor_sync(0xffffffffu, send.z, 16);
            rec.w = __shfl_xor_sync(0xffffffffu, send.w, 16);
            keep.x += rec.x; keep.y += rec.y; keep.z += rec.z; keep.w += rec.w;
            *reinterpret_cast<float4*>(myred + (q << 2)) = keep;
        }
        __syncthreads();

        // ---- reduce 16 k-slice partials, finish, publish ----
        {
            const float* rr = red + ro * CSTR + cp;
            float s0 = 0.f, s1 = 0.f;
            #pragma unroll
            for (int w = 0; w < 16; ++w) {
                s0 += rr[(w << 5) * CSTR];
                s1 += rr[(w << 5) * CSTR + 1];
            }
            float v0 = tanhf(s0 + fmaf(wx, xs[cp],     bh));
            float v1 = tanhf(s1 + fmaf(wx, xs[cp + 1], bh));
            const int wbuf = (s + 1) % 3;
            *reinterpret_cast<float2*>(&g_h[wbuf][rbase + ro][cbase + cp]) =
                make_float2(v0, v1);
        }

        __syncthreads();
        if (tid == 0)
            asm volatile("st.release.gpu.u32 [%0], %1;"
                         :: "l"(&g_flag[bg][rg][0]), "r"((unsigned)(s + 1)) : "memory");
    }

    // ---- final projection (row-group 0 CTAs); h_1024 in buf 1024%3 == 1 ----
    if (rg == 0) {
        {
            if (lane == 0) wait_flag(&g_flag[bg][j0][0], (unsigned)TT);
            __syncwarp();
            const int rbuf = TT % 3;
            const float* src = &g_h[rbuf][j0 << 5][cbase];
            float*       dst = hs + (j0 << 5) * H_PAD;
            #pragma unroll
            for (int p = 0; p < 8; ++p) {
                int k = (p << 2) + lk;
                float4 v = __ldcg(reinterpret_cast<const float4*>(src + k * BB + lc4));
                *reinterpret_cast<float4*>(dst + k * H_PAD + lc4) = v;
            }
        }
        __syncthreads();

        // reuse reduction buffer for W_ph (10*512 floats)
        float* Wp = red;
        for (int i = tid; i < (NCLS * HH) / 4; i += NTHR) {
            float4 v = *reinterpret_cast<const float4*>(W_ph + (i << 2));
            *reinterpret_cast<float4*>(Wp + (i << 2)) = v;
        }
        __syncthreads();

        for (int idx = tid; idx < BT * NCLS; idx += NTHR) {
            int cl = idx / NCLS;
            int n  = idx - cl * NCLS;
            float acc = b_p[n];
            const float* wrow = Wp + n * HH;
            const float* hcol = hs + cl;
            #pragma unroll 8
            for (int k = 0; k < HH; ++k)
                acc = fmaf(wrow[k], hcol[k * H_PAD], acc);
            out[(cbase + cl) * NCLS + n] = acc;
        }
    }
}

extern "C" void kernel_launch(void* const* d_in, const int* in_sizes, int n_in,
                              void* d_out, int out_size) {
    const float* x      = (const float*)d_in[0];
    const float* h_init = (const float*)d_in[1];
    const float* W_hx   = (const float*)d_in[2];
    const float* W_hh   = (const float*)d_in[3];
    const float* b_h    = (const float*)d_in[4];
    const float* W_ph   = (const float*)d_in[5];
    const float* b_p    = (const float*)d_in[6];
    float* out = (float*)d_out;

    void* flagp = nullptr;
    cudaGetSymbolAddress(&flagp, g_flag);
    cudaMemsetAsync(flagp, 0, BGN * RGN * 32 * sizeof(unsigned), 0);

    cudaFuncSetAttribute(rnn_persistent,
                         cudaFuncAttributeMaxDynamicSharedMemorySize, SMEM_BYTES);

    rnn_persistent<<<NCTA, NTHR, SMEM_BYTES, 0>>>(x, h_init, W_hx, W_hh, b_h,
                                                  W_ph, b_p, out);
}

// round 16
// speedup vs baseline: 1.2255x; 1.0438x over previous
#include <cuda_runtime.h>

// VanillaRNN persistent kernel for GB300 (sm_103a) — round 15: 2 CTAs/SM.
// h_{t+1} = tanh(W_hx * x_t + W_hh @ h_t + b_h), 1024 steps; p = W_ph @ h + b_p.
//
// 256 persistent CTAs = 32 row-groups x 8 batch-groups; 16 rows x 32 cols each;
// 256 threads (8 warps), __launch_bounds__(256,2) -> 2 CTAs per SM so one CTA's
// sync/exchange bubbles are filled by the other's compute.
//  - warp = 64-k slice; lane = (rp,kh,ch): 2 rows x 16 cols x 32 k.
//  - h LDS: ld.shared.v2.u64 with 4 distinct chunks/wavefront (64 useful B/wf,
//    conflict-free banks b,b+4,b+16,b+20).
//  - FFMA2 accumulation (R14-proven); kh combined with one shfl_xor(8) level;
//    ch needs no combine (distinct columns).
//  - reduce reads via LDS.64 (bank-minimal). Flags/triple-buffer as R14.

#define HH    512
#define BB    256
#define TT    1024
#define NCLS  10

#define RGN   32
#define BGN   8
#define HR    16
#define BT    32
#define NCTA  (RGN * BGN)   // 256
#define NTHR  256
#define NW    8

#define H_PAD 36
#define CSTR  36

#define SMEM_FLOATS (HH * H_PAD + NW * HR * CSTR + BT)
#define SMEM_BYTES  (SMEM_FLOATS * 4)     // 92,288 B -> 2 CTAs/SM

typedef unsigned long long u64;

__device__ float    g_h[3][HH][BB];        // triple-buffered hidden state
__device__ unsigned g_flag[BGN][RGN][32];  // per-tile publish counters, 128B apart

__device__ __forceinline__ void wait_flag(const unsigned* p, unsigned target) {
    unsigned v;
    do {
        asm volatile("ld.acquire.gpu.u32 %0, [%1];" : "=r"(v) : "l"(p) : "memory");
    } while (v < target);
}

__device__ __forceinline__ u64 ffma2(u64 a, u64 b, u64 c) {
    u64 d;
    asm("fma.rn.f32x2 %0, %1, %2, %3;" : "=l"(d) : "l"(a), "l"(b), "l"(c));
    return d;
}

__global__ void __launch_bounds__(NTHR, 2) rnn_persistent(
    const float* __restrict__ x,       // [BB][TT]
    const float* __restrict__ h_init,  // [HH]
    const float* __restrict__ W_hx,    // [HH]
    const float* __restrict__ W_hh,    // [HH][HH]
    const float* __restrict__ b_h,     // [HH]
    const float* __restrict__ W_ph,    // [NCLS][HH]
    const float* __restrict__ b_p,     // [NCLS]
    float* __restrict__ out)           // [BB][NCLS]
{
    extern __shared__ float smem[];
    float* hs  = smem;                        // [HH][H_PAD]
    float* red = smem + HH * H_PAD;           // [NW*HR][CSTR]
    float* xs  = red + NW * HR * CSTR;        // [BT]

    const int tid   = threadIdx.x;
    const int lane  = tid & 31;
    const int wid   = tid >> 5;        // 0..7 : 64-wide k-slice
    const int cta   = blockIdx.x;
    const int rg    = cta >> 3;        // 0..31
    const int bg    = cta & 7;
    const int rbase = rg * HR;
    const int cbase = bg * BT;
    const int k0    = wid << 6;        // 64*wid

    // ---- lane decomposition ----
    const int rp = lane & 7;           // row pair
    const int kh = (lane >> 3) & 1;    // k parity
    const int ch = lane >> 4;          // col half
    const int r0 = rp << 1;            // local rows r0, r0+1
    const int cb = ch << 4;            // local col base (16 cols)

    // ---- W_hh -> registers: 2 rows x 32 k (k = k0 + 2i + kh) ----
    float w0[32], w1[32];
    {
        const float* wr0 = W_hh + (rbase + r0)     * HH + k0 + kh;
        const float* wr1 = W_hh + (rbase + r0 + 1) * HH + k0 + kh;
        #pragma unroll
        for (int i = 0; i < 32; ++i) {
            w0[i] = wr0[i << 1];
            w1[i] = wr1[i << 1];
        }
    }

    // ---- init hs with h_init broadcast ----
    for (int k = tid; k < HH; k += NTHR) {
        float v = h_init[k];
        float* row = hs + k * H_PAD;
        #pragma unroll
        for (int c = 0; c < BT; ++c) row[c] = v;
    }

    // ---- reduce/publish mapping: thread -> (row ro 0..15, col pair cp) ----
    const int ro = tid >> 4;            // 0..15
    const int cp = (tid & 15) << 1;     // 0,2,...,30
    const float bh = b_h[rbase + ro];
    const float wx = W_hx[rbase + ro];

    // ---- refresh mapping: warp wid covers chunks (rg + wid + 8t) & 31 ----
    const int lk  = lane >> 3;          // 0..3
    const int lc4 = (lane & 7) << 2;    // 0,4,...,28

    const unsigned hb_s =
        (unsigned)__cvta_generic_to_shared(hs + (k0 + kh) * H_PAD + cb);

    __syncthreads();

    for (int s = 0; s < TT; ++s) {
        // ---- distributed refresh: 4 chunks of 16 rows per warp (skip s=0) ----
        if (s > 0) {
            const int rbuf = s % 3;
            if (lane < 4)
                wait_flag(&g_flag[bg][(rg + wid + (lane << 3)) & 31][0], (unsigned)s);
            __syncwarp();
            #pragma unroll
            for (int t = 0; t < 4; ++t) {
                const int j = (rg + wid + (t << 3)) & 31;
                const float* src = &g_h[rbuf][j << 4][cbase];
                float*       dst = hs + (j << 4) * H_PAD;
                #pragma unroll
                for (int p = 0; p < 4; ++p) {
                    int k = (p << 2) + lk;
                    float4 v = __ldcg(reinterpret_cast<const float4*>(src + k * BB + lc4));
                    *reinterpret_cast<float4*>(dst + k * H_PAD + lc4) = v;
                }
            }
        }
        if (tid < BT) xs[tid] = x[(cbase + tid) * TT + s];
        __syncthreads();

        // ---- packed partial GEMV: 2 rows x 32 k x 16 cols via FFMA2 ----
        u64 P0[8], P1[8];
        #pragma unroll
        for (int q = 0; q < 8; ++q) { P0[q] = 0ull; P1[q] = 0ull; }

        #pragma unroll
        for (int i = 0; i < 32; ++i) {
            u64 dw0, dw1;
            asm("mov.b64 %0, {%1, %1};" : "=l"(dw0) : "f"(w0[i]));
            asm("mov.b64 %0, {%1, %1};" : "=l"(dw1) : "f"(w1[i]));
            const unsigned hr = hb_s + (unsigned)((i << 1) * (H_PAD * 4));
            #pragma unroll
            for (int q = 0; q < 4; ++q) {
                u64 hA, hB;
                asm("ld.shared.v2.u64 {%0, %1}, [%2];"
                    : "=l"(hA), "=l"(hB) : "r"(hr + (q << 4)));
                P0[2*q]     = ffma2(dw0, hA, P0[2*q]);
                P0[2*q + 1] = ffma2(dw0, hB, P0[2*q + 1]);
                P1[2*q]     = ffma2(dw1, hA, P1[2*q]);
                P1[2*q + 1] = ffma2(dw1, hB, P1[2*q + 1]);
            }
        }

        // ---- unpack, combine kh halves (partner = lane ^ 8), STS keep-row ----
        float4 A0[4], A1[4];
        #pragma unroll
        for (int q = 0; q < 4; ++q) {
            asm("mov.b64 {%0, %1}, %2;" : "=f"(A0[q].x), "=f"(A0[q].y) : "l"(P0[2*q]));
            asm("mov.b64 {%0, %1}, %2;" : "=f"(A0[q].z), "=f"(A0[q].w) : "l"(P0[2*q+1]));
            asm("mov.b64 {%0, %1}, %2;" : "=f"(A1[q].x), "=f"(A1[q].y) : "l"(P1[2*q]));
            asm("mov.b64 {%0, %1}, %2;" : "=f"(A1[q].z), "=f"(A1[q].w) : "l"(P1[2*q+1]));
        }

        const int myrow = r0 + kh;
        float* myred = red + ((wid << 4) + myrow) * CSTR + cb;
        #pragma unroll
        for (int q = 0; q < 4; ++q) {
            float4 send = kh ? A0[q] : A1[q];
            float4 keep = kh ? A1[q] : A0[q];
            float4 rec;
            rec.x = __shfl_xor_sync(0xffffffffu, send.x, 8);
            rec.y = __shfl_xor_sync(0xffffffffu, send.y, 8);
            rec.z = __shfl_xor_sync(0xffffffffu, send.z, 8);
            rec.w = __shfl_xor_sync(0xffffffffu, send.w, 8);
            keep.x += rec.x; keep.y += rec.y; keep.z += rec.z; keep.w += rec.w;
            *reinterpret_cast<float4*>(myred + (q << 2)) = keep;
        }
        __syncthreads();

        // ---- reduce 8 k-slice partials (LDS.64), finish, publish ----
        {
            const float* rr = red + ro * CSTR + cp;
            float s0 = 0.f, s1 = 0.f;
            #pragma unroll
            for (int w = 0; w < 8; ++w) {
                float2 p = *reinterpret_cast<const float2*>(rr + (w << 4) * CSTR);
                s0 += p.x; s1 += p.y;
            }
            float v0 = tanhf(s0 + fmaf(wx, xs[cp],     bh));
            float v1 = tanhf(s1 + fmaf(wx, xs[cp + 1], bh));
            const int wbuf = (s + 1) % 3;
            *reinterpret_cast<float2*>(&g_h[wbuf][rbase + ro][cbase + cp]) =
                make_float2(v0, v1);
        }

        __syncthreads();
        if (tid == 0)
            asm volatile("st.release.gpu.u32 [%0], %1;"
                         :: "l"(&g_flag[bg][rg][0]), "r"((unsigned)(s + 1)) : "memory");
    }

    // ---- final projection (row-group 0 CTAs); h_1024 in buf 1024%3 == 1 ----
    if (rg == 0) {
        {
            const int rbuf = TT % 3;
            if (lane < 4)
                wait_flag(&g_flag[bg][(rg + wid + (lane << 3)) & 31][0], (unsigned)TT);
            __syncwarp();
            #pragma unroll
            for (int t = 0; t < 4; ++t) {
                const int j = (rg + wid + (t << 3)) & 31;
                const float* src = &g_h[rbuf][j << 4][cbase];
                float*       dst = hs + (j << 4) * H_PAD;
                #pragma unroll
                for (int p = 0; p < 4; ++p) {
                    int k = (p << 2) + lk;
                    float4 v = __ldcg(reinterpret_cast<const float4*>(src + k * BB + lc4));
                    *reinterpret_cast<float4*>(dst + k * H_PAD + lc4) = v;
                }
            }
        }
        __syncthreads();

        for (int idx = tid; idx < BT * NCLS; idx += NTHR) {
            int cl = idx / NCLS;
            int n  = idx - cl * NCLS;
            float acc = b_p[n];
            const float* wrow = W_ph + n * HH;   // direct from global (L2-hot)
            const float* hcol = hs + cl;
            #pragma unroll 8
            for (int k = 0; k < HH; ++k)
                acc = fmaf(__ldg(wrow + k), hcol[k * H_PAD], acc);
            out[(cbase + cl) * NCLS + n] = acc;
        }
    }
}

extern "C" void kernel_launch(void* const* d_in, const int* in_sizes, int n_in,
                              void* d_out, int out_size) {
    const float* x      = (const float*)d_in[0];
    const float* h_init = (const float*)d_in[1];
    const float* W_hx   = (const float*)d_in[2];
    const float* W_hh   = (const float*)d_in[3];
    const float* b_h    = (const float*)d_in[4];
    const float* W_ph   = (const float*)d_in[5];
    const float* b_p    = (const float*)d_in[6];
    float* out = (float*)d_out;

    void* flagp = nullptr;
    cudaGetSymbolAddress(&flagp, g_flag);
    cudaMemsetAsync(flagp, 0, BGN * RGN * 32 * sizeof(unsigned), 0);

    cudaFuncSetAttribute(rnn_persistent,
                         cudaFuncAttributeMaxDynamicSharedMemorySize, SMEM_BYTES);

    rnn_persistent<<<NCTA, NTHR, SMEM_BYTES, 0>>>(x, h_init, W_hx, W_hh, b_h,
                                                  W_ph, b_p, out);
}